// round 15
// baseline (speedup 1.0000x reference)
#include <cuda_runtime.h>
#include <math.h>
#include <limits.h>
#include <stdint.h>

// ---------------- problem constants ----------------
#define BATCH   256
#define LSEQ    34
#define DMODEL  128
#define DI      256
#define NSTATE  128
#define BAND    189
#define MROWS   (BATCH*LSEQ)   // 8704
#define KFLAT   (LSEQ*DMODEL)  // 4352
#define KCH     544            // 4352 / 8 slices
#define KSLICES 8

// ---------------- scratch (device globals; no runtime alloc) ----------------
__device__ float g_xn   [MROWS*DMODEL];
__device__ float g_xp   [MROWS*DI];
__device__ float g_xc1  [MROWS*DI];
__device__ float g_xc   [MROWS*DI];
__device__ float g_delta[MROWS*DI];
__device__ float g_dg   [MROWS*DI];
__device__ float g_Bm   [MROWS*NSTATE];
__device__ float g_Cm   [MROWS*NSTATE];
__device__ float g_xs   [MROWS*DI];   // holds silu(xs)*dg after scan
__device__ float g_yout [MROWS*DMODEL];
__device__ float g_fp   [KSLICES*BATCH*64];   // fnn1 split-K partials
__device__ float g_aval [DI];         // per-row A value (if uniform)
__device__ int   g_flag [1];          // 1 = all A rows uniform

// ---------------- math helpers ----------------
__device__ __forceinline__ float siluf(float x)     { return x / (1.0f + __expf(-x)); }
__device__ __forceinline__ float softplusf(float x) { return x > 15.0f ? x : log1pf(__expf(x)); }
__device__ __forceinline__ float leakyf(float x)    { return x >= 0.0f ? x : 0.01f * x; }

// ---------------- PTX helpers ----------------
__device__ __forceinline__ void cp16(uint32_t dst, const void* src) {
    asm volatile("cp.async.cg.shared.global [%0], [%1], 16;" :: "r"(dst), "l"(src));
}
__device__ __forceinline__ void ldsm_x4(uint32_t& r0, uint32_t& r1, uint32_t& r2, uint32_t& r3,
                                        uint32_t addr) {
    asm volatile("ldmatrix.sync.aligned.m8n8.x4.shared.b16 {%0,%1,%2,%3}, [%4];"
                 : "=r"(r0), "=r"(r1), "=r"(r2), "=r"(r3) : "r"(addr));
}
__device__ __forceinline__ void mma_tf32(float* c, const uint32_t* a, const uint32_t* b) {
    asm volatile("mma.sync.aligned.m16n8k8.row.col.f32.tf32.tf32.f32 "
                 "{%0,%1,%2,%3},{%4,%5,%6,%7},{%8,%9},{%0,%1,%2,%3};"
                 : "+f"(c[0]), "+f"(c[1]), "+f"(c[2]), "+f"(c[3])
                 : "r"(a[0]), "r"(a[1]), "r"(a[2]), "r"(a[3]), "r"(b[0]), "r"(b[1]));
}

// =====================================================================
// K1: conv1d + LeakyReLU + RMSNorm -> xn   (+ A-uniformity prep block)
// =====================================================================
__global__ __launch_bounds__(256)
void k_conv_prep(const float* __restrict__ x, const float* __restrict__ cw,
                 const float* __restrict__ cb, const float* __restrict__ nw,
                 const float* __restrict__ A,  float* __restrict__ xn,
                 int* __restrict__ flag, float* __restrict__ aval)
{
    int tid = threadIdx.x;

    if (blockIdx.x == BATCH) {
        int d = tid;
        const float* row = A + (size_t)d * NSTATE;
        float a0 = row[0];
        bool uni = true;
        #pragma unroll 8
        for (int n = 1; n < NSTATE; n++) uni &= (row[n] == a0);
        aval[d] = a0;
        int all = __syncthreads_and(uni ? 1 : 0);
        if (d == 0) flag[0] = all;
        return;
    }

    int b = blockIdx.x;
    int c = tid;
    bool active = (c < 128);

    __shared__ float sx[BAND];
    __shared__ float sw[128*21];
    __shared__ float red[2][4];

    for (int i = tid; i < 128*20; i += 256) sw[(i/20)*21 + (i%20)] = cw[i];
    for (int i = tid; i < BAND; i += 256)   sx[i] = x[b*BAND + i];
    __syncthreads();

    float wreg[20];
    float cbv = 0.f, nwv = 0.f;
    if (active) {
        #pragma unroll
        for (int k = 0; k < 20; k++) wreg[k] = sw[c*21 + k];
        cbv = cb[c]; nwv = nw[c];
    }

    #pragma unroll 1
    for (int l = 0; l < LSEQ; l++) {
        float acc = cbv;
        if (active) {
            #pragma unroll
            for (int k = 0; k < 20; k++) acc = fmaf(sx[l*5 + k], wreg[k], acc);
            acc = leakyf(acc);
        }
        float sq = acc * acc;
        #pragma unroll
        for (int off = 16; off; off >>= 1) sq += __shfl_xor_sync(0xffffffffu, sq, off);
        int pb = l & 1;
        if (active && (c & 31) == 0) red[pb][c >> 5] = sq;
        __syncthreads();
        if (active) {
            float inv = rsqrtf((red[pb][0]+red[pb][1]+red[pb][2]+red[pb][3])
                               * (1.0f/128.0f) + 1e-5f);
            xn[(b*LSEQ + l)*DMODEL + c] = acc * inv * nwv;
        }
    }
}

// =====================================================================
// Segmented TF32 tensor-core GEMM, 2-stage cp.async double buffer, BK=32,
// one wait+sync per iteration, 3 CTAs/SM.
// =====================================================================
#define ACT_NONE 0
#define ACT_SILU 1
#define ACT_SOFTPLUS 2

struct Seg3 {
    const float* W[3];
    const float* bias[3];
    float*       out[3];
    int start[4];
    int act[3];
    int ldout[3];
};

template<int BM, int BN, int WM, int WN>
__global__ __launch_bounds__(256, 3)
void gemm_tc(const float* __restrict__ A, Seg3 segs, int K)
{
    constexpr int BK   = 32;
    constexpr int LD   = BK + 4;
    constexpr int STG  = 2;
    constexpr int CPR  = BK / 4;
    constexpr int WTM  = BM / WM;
    constexpr int WTN  = BN / WN;
    constexpr int AM   = WTM / 16;
    constexpr int AN   = WTN / 8;

    extern __shared__ __align__(16) float smem[];
    float* As = smem;
    float* Ws = smem + STG * BM * LD;

    const int tid  = threadIdx.x;
    const int lane = tid & 31;
    const int warp = tid >> 5;
    const int wm   = warp % WM;
    const int wn   = warp / WM;

    const int bm = blockIdx.y * BM;
    const int n0 = blockIdx.x * BN;

    int s = 0;
    if (n0 >= segs.start[1]) s = 1;
    if (n0 >= segs.start[2]) s = 2;
    const float* __restrict__ W = segs.W[s];
    const int ln0 = n0 - segs.start[s];

    const uint32_t sA0 = (uint32_t)__cvta_generic_to_shared(As);
    const uint32_t sW0 = (uint32_t)__cvta_generic_to_shared(Ws);

    float acc[AM][AN][4];
    #pragma unroll
    for (int i = 0; i < AM; i++)
        #pragma unroll
        for (int j = 0; j < AN; j++)
            #pragma unroll
            for (int q = 0; q < 4; q++) acc[i][j][q] = 0.0f;

    auto load_tiles = [&](int buf, int k0) {
        uint32_t dA = sA0 + (uint32_t)buf * (BM*LD*4);
        #pragma unroll
        for (int t = 0; t < (BM*CPR)/256; t++) {
            int c = tid + t*256;
            int row = c / CPR, kc = (c % CPR)*4;
            cp16(dA + (uint32_t)(row*LD + kc)*4, A + (size_t)(bm+row)*K + k0 + kc);
        }
        uint32_t dW = sW0 + (uint32_t)buf * (BN*LD*4);
        #pragma unroll
        for (int t = 0; t < (BN*CPR)/256; t++) {
            int c = tid + t*256;
            int row = c / CPR, kc = (c % CPR)*4;
            cp16(dW + (uint32_t)(row*LD + kc)*4, W + (size_t)(ln0+row)*K + k0 + kc);
        }
        asm volatile("cp.async.commit_group;");
    };

    const int a_row_in = ((lane >> 3) & 1) * 8 + (lane & 7);
    const int a_bc_hi  = (lane >= 16) ? 16 : 0;
    const int b_row_in = ((lane >= 16) ? 8 : 0) + (lane & 7);
    const int b_bc_hi  = ((lane >> 3) & 1) * 16;

    auto compute = [&](int buf) {
        const uint32_t aB = sA0 + (uint32_t)buf * (BM*LD*4);
        const uint32_t wB = sW0 + (uint32_t)buf * (BN*LD*4);
        #pragma unroll
        for (int k8 = 0; k8 < BK; k8 += 8) {
            uint32_t af[AM][4];
            #pragma unroll
            for (int mi = 0; mi < AM; mi++) {
                int r = wm*WTM + mi*16 + a_row_in;
                ldsm_x4(af[mi][0], af[mi][1], af[mi][2], af[mi][3],
                        aB + (uint32_t)(r*LD)*4 + (uint32_t)(k8*4 + a_bc_hi));
            }
            uint32_t bf[AN][2];
            #pragma unroll
            for (int nj = 0; nj < AN; nj += 2) {
                int r = wn*WTN + nj*8 + b_row_in;
                ldsm_x4(bf[nj][0], bf[nj][1], bf[nj+1][0], bf[nj+1][1],
                        wB + (uint32_t)(r*LD)*4 + (uint32_t)(k8*4 + b_bc_hi));
            }
            #pragma unroll
            for (int mi = 0; mi < AM; mi++)
                #pragma unroll
                for (int nj = 0; nj < AN; nj++)
                    mma_tf32(acc[mi][nj], af[mi], bf[nj]);
        }
    };

    // ---- 2-stage mainloop: issue next load, compute current, wait+sync.
    const int NIT = K / BK;
    load_tiles(0, 0);
    asm volatile("cp.async.wait_group 0;");
    __syncthreads();
    int buf = 0;
    for (int it = 0; it < NIT; it++) {
        if (it + 1 < NIT) load_tiles(buf ^ 1, (it + 1) * BK);
        compute(buf);
        if (it + 1 < NIT) {
            asm volatile("cp.async.wait_group 0;");
            __syncthreads();   // loads visible AND all warps done reading buf
        }
        buf ^= 1;
    }

    __syncthreads();
    const float* __restrict__ bias = segs.bias[s];
    float* __restrict__ outp = segs.out[s];
    const int ld  = segs.ldout[s];
    const int act = segs.act[s];

    #pragma unroll
    for (int mi = 0; mi < AM; mi++) {
        int row0 = bm + wm*WTM + mi*16 + (lane >> 2);
        #pragma unroll
        for (int nj = 0; nj < AN; nj++) {
            int col = ln0 + wn*WTN + nj*8 + ((lane & 3) << 1);
            float b0 = bias[col], b1 = bias[col+1];
            float v0 = acc[mi][nj][0] + b0;
            float v1 = acc[mi][nj][1] + b1;
            float v2 = acc[mi][nj][2] + b0;
            float v3 = acc[mi][nj][3] + b1;
            if (act == ACT_SILU) {
                v0 = siluf(v0); v1 = siluf(v1); v2 = siluf(v2); v3 = siluf(v3);
            } else if (act == ACT_SOFTPLUS) {
                v0 = softplusf(v0); v1 = softplusf(v1);
                v2 = softplusf(v2); v3 = softplusf(v3);
            }
            *(float2*)(outp + (size_t)row0*ld + col)     = make_float2(v0, v1);
            *(float2*)(outp + (size_t)(row0+8)*ld + col) = make_float2(v2, v3);
        }
    }
}

template<int BM, int BN>
constexpr int gemm_smem_bytes() { return 2 * (BM + BN) * 36 * 4; }

// =====================================================================
// K3: seq-conv + silu. 128 threads: thread = (j-quad, lo-quarter).
// grid (BATCH, 2).
// =====================================================================
__global__ __launch_bounds__(128)
void k_seqconv(const float* __restrict__ xp, const float* __restrict__ w,
               const float* __restrict__ bias, float* __restrict__ out)
{
    int b  = blockIdx.x;
    int jb = blockIdx.y * 128;
    int tid = threadIdx.x;
    int jq  = tid & 31;
    int q   = tid >> 5;
    const int j   = jq * 4;
    const int lo0 = (q < 2) ? q*9 : 18 + (q-2)*8;
    const int nlo = (q < 2) ? 9 : 8;

    __shared__ __align__(16) float4 sw4[LSEQ*LSEQ];   // [li][lo]
    __shared__ __align__(8)  float sx[LSEQ][130];
    __shared__ float sb[LSEQ];

    for (int i = tid; i < LSEQ*LSEQ; i += 128) {
        int li = i / LSEQ, lo = i % LSEQ;
        const float* wp = w + (lo*LSEQ + li)*3;
        sw4[i] = make_float4(wp[0], wp[1], wp[2], 0.0f);
    }
    if (tid < LSEQ) sb[tid] = bias[tid];
    for (int i = tid; i < LSEQ*128; i += 128) {
        int l = i >> 7, jj = i & 127;
        sx[l][jj+1] = xp[(size_t)(b*LSEQ + l)*DI + jb + jj];
    }
    if (tid < LSEQ) {
        sx[tid][0]   = (jb == 0)   ? 0.0f : xp[(size_t)(b*LSEQ + tid)*DI + jb - 1];
        sx[tid][129] = (jb == 128) ? 0.0f : xp[(size_t)(b*LSEQ + tid)*DI + jb + 128];
    }
    __syncthreads();

    float acc[9][4];
    #pragma unroll
    for (int r = 0; r < 9; r++) {
        float bv = (r < nlo) ? sb[lo0 + r] : 0.0f;
        acc[r][0] = bv; acc[r][1] = bv; acc[r][2] = bv; acc[r][3] = bv;
    }

    #pragma unroll 2
    for (int li = 0; li < LSEQ; li++) {
        float2 x01 = *(const float2*)&sx[li][j];
        float2 x23 = *(const float2*)&sx[li][j+2];
        float2 x45 = *(const float2*)&sx[li][j+4];
        float x0 = x01.x, x1 = x01.y, x2 = x23.x, x3 = x23.y, x4 = x45.x, x5 = x45.y;
        const float4* wr = &sw4[li*LSEQ + lo0];
        #pragma unroll
        for (int r = 0; r < 9; r++) {
            if (r < nlo) {
                float4 wv = wr[r];
                acc[r][0] = fmaf(wv.x, x0, fmaf(wv.y, x1, fmaf(wv.z, x2, acc[r][0])));
                acc[r][1] = fmaf(wv.x, x1, fmaf(wv.y, x2, fmaf(wv.z, x3, acc[r][1])));
                acc[r][2] = fmaf(wv.x, x2, fmaf(wv.y, x3, fmaf(wv.z, x4, acc[r][2])));
                acc[r][3] = fmaf(wv.x, x3, fmaf(wv.y, x4, fmaf(wv.z, x5, acc[r][3])));
            }
        }
    }
    #pragma unroll
    for (int r = 0; r < 9; r++) {
        if (r < nlo) {
            float4 v = make_float4(siluf(acc[r][0]), siluf(acc[r][1]),
                                   siluf(acc[r][2]), siluf(acc[r][3]));
            *(float4*)(out + (size_t)(b*LSEQ + lo0 + r)*DI + jb + j) = v;
        }
    }
}

// =====================================================================
// K7: scan (merged fast/fallback). grid BATCH x 256.
// =====================================================================
__global__ __launch_bounds__(256)
void k_scan(const float* __restrict__ delta, const float* __restrict__ Bm,
            const float* __restrict__ Cm,    const float* __restrict__ xc,
            const float* __restrict__ A,     const float* __restrict__ dgp,
            const float* __restrict__ aval,  const int* __restrict__ flag,
            float* __restrict__ xs)
{
    int b = blockIdx.x;
    int tid = threadIdx.x;
    int lane = tid & 31, warp = tid >> 5;

    if (flag[0]) {
        __shared__ float sC [LSEQ*132];
        __shared__ float sBt[NSTATE*36];
        __shared__ float sG [LSEQ*36];

        for (int i = tid; i < LSEQ*NSTATE; i += 256) {
            int l = i >> 7, n = i & 127;
            sC[l*132 + n] = Cm[(size_t)b*LSEQ*NSTATE + i];
            sBt[n*36 + l] = Bm[(size_t)b*LSEQ*NSTATE + i];
        }
        __syncthreads();

        {
            int l0 = warp * 4;
            float a0[4], a1[4];
            #pragma unroll
            for (int r = 0; r < 4; r++) { a0[r] = 0.f; a1[r] = 0.f; }
            #pragma unroll 4
            for (int n = 0; n < NSTATE; n++) {
                float bv0 = sBt[n*36 + lane];
                float bv1 = (lane < 2) ? sBt[n*36 + 32 + lane] : 0.0f;
                #pragma unroll
                for (int r = 0; r < 4; r++) {
                    float cv = sC[(l0+r)*132 + n];
                    a0[r] = fmaf(cv, bv0, a0[r]);
                    a1[r] = fmaf(cv, bv1, a1[r]);
                }
            }
            #pragma unroll
            for (int r = 0; r < 4; r++) {
                sG[(l0+r)*36 + lane] = a0[r];
                if (lane < 2) sG[(l0+r)*36 + 32 + lane] = a1[r];
            }
            if (warp < 2) {
                int l = 32 + warp;
                float e0 = 0.f, e1 = 0.f;
                #pragma unroll 4
                for (int n = 0; n < NSTATE; n++) {
                    float bv0 = sBt[n*36 + lane];
                    float bv1 = (lane < 2) ? sBt[n*36 + 32 + lane] : 0.0f;
                    float cv  = sC[l*132 + n];
                    e0 = fmaf(cv, bv0, e0);
                    e1 = fmaf(cv, bv1, e1);
                }
                sG[l*36 + lane] = e0;
                if (lane < 2) sG[l*36 + 32 + lane] = e1;
            }
        }

        int d = tid;
        const float av = aval[d];

        float S[LSEQ], dx[LSEQ];
        #pragma unroll
        for (int l = 0; l < LSEQ; l++) {
            float dl = delta[((size_t)b*LSEQ + l)*DI + d];
            float xv = xc   [((size_t)b*LSEQ + l)*DI + d];
            S[l]  = dl * av;
            dx[l] = dl * xv;
        }
        #pragma unroll
        for (int l = 1; l < LSEQ; l++) S[l] += S[l-1];
        float m = fmaxf(S[0], S[LSEQ-1]);
        #pragma unroll
        for (int t = 0; t < LSEQ; t++) dx[t] *= __expf(m - S[t]);

        __syncthreads();

        #pragma unroll
        for (int l = 0; l < LSEQ; l++) {
            float y = 0.0f;
            const float* gr = &sG[l*36];
            #pragma unroll
            for (int t = 0; t <= l; t++)
                y = fmaf(gr[t], dx[t], y);
            float o = __expf(S[l] - m) * y;
            size_t idx = ((size_t)b*LSEQ + l)*DI + d;
            xs[idx] = siluf(o) * dgp[idx];
        }
    } else {
        // general-A fallback: warp per channel, strided. Correct, slow.
        for (int dd = warp; dd < DI; dd += 8) {
            float a0 = A[dd*NSTATE + lane +  0];
            float a1 = A[dd*NSTATE + lane + 32];
            float a2 = A[dd*NSTATE + lane + 64];
            float a3 = A[dd*NSTATE + lane + 96];
            float h0 = 0.f, h1 = 0.f, h2 = 0.f, h3 = 0.f;
            #pragma unroll 1
            for (int l = 0; l < LSEQ; l++) {
                size_t ridx = (size_t)b*LSEQ + l;
                float dv = delta[ridx*DI + dd];
                float xv = xc   [ridx*DI + dd];
                float dx = dv * xv;
                const float* Brow = Bm + ridx*NSTATE;
                const float* Crow = Cm + ridx*NSTATE;
                h0 = fmaf(__expf(dv*a0), h0, dx * Brow[lane +  0]);
                h1 = fmaf(__expf(dv*a1), h1, dx * Brow[lane + 32]);
                h2 = fmaf(__expf(dv*a2), h2, dx * Brow[lane + 64]);
                h3 = fmaf(__expf(dv*a3), h3, dx * Brow[lane + 96]);
                float acc = Crow[lane+0]*h0 + Crow[lane+32]*h1
                          + Crow[lane+64]*h2 + Crow[lane+96]*h3;
                #pragma unroll
                for (int off = 16; off; off >>= 1)
                    acc += __shfl_down_sync(0xffffffffu, acc, off);
                if (lane == 0) {
                    size_t idx = ridx*DI + dd;
                    xs[idx] = siluf(acc) * dgp[idx];
                }
            }
        }
    }
}

// =====================================================================
// K9a: FNN1 split-K partials. grid (64, 8): 4 batches x 544-K-slice.
// =====================================================================
__global__ __launch_bounds__(256)
void k_fnn1p(const float* __restrict__ yflat, const float* __restrict__ w1,
             float* __restrict__ fp)
{
    int bg = blockIdx.x;
    int ks = blockIdx.y;
    int tid = threadIdx.x;
    int b0 = bg*4, k0 = ks*KCH;

    __shared__ float sy[4][KCH];
    for (int i = tid; i < 4*KCH; i += 256) {
        int bb = i / KCH, kk = i % KCH;
        sy[bb][kk] = yflat[(size_t)(b0+bb)*KFLAT + k0 + kk];
    }
    __syncthreads();

    int o = tid & 63, bb = tid >> 6;
    const float* wr = w1 + (size_t)o*KFLAT + k0;
    const float* yr = sy[bb];
    float acc = 0.0f;
    #pragma unroll 4
    for (int i = 0; i < KCH; i += 4) {
        float4 wv = *(const float4*)(wr + i);
        acc = fmaf(wv.x, yr[i+0], acc);
        acc = fmaf(wv.y, yr[i+1], acc);
        acc = fmaf(wv.z, yr[i+2], acc);
        acc = fmaf(wv.w, yr[i+3], acc);
    }
    fp[((size_t)ks*BATCH + b0 + bb)*64 + o] = acc;
}

// =====================================================================
// K9b: FNN finish: reduce partials + bias + leaky, then FNN2.
// =====================================================================
__global__ __launch_bounds__(64)
void k_fnn2(const float* __restrict__ fp, const float* __restrict__ b1,
            const float* __restrict__ w2, const float* __restrict__ b2,
            float* __restrict__ out)
{
    int b = blockIdx.x;
    int o = threadIdx.x;
    __shared__ float sf[64];

    float acc = b1[o];
    #pragma unroll
    for (int ks = 0; ks < KSLICES; ks++)
        acc += fp[((size_t)ks*BATCH + b)*64 + o];
    sf[o] = leakyf(acc);
    __syncthreads();

    if (o < 32) {
        float a2 = b2[o];
        #pragma unroll 8
        for (int j = 0; j < 64; j++) a2 = fmaf(sf[j], w2[o*64 + j], a2);
        out[(size_t)b*32 + o] = a2;
    }
}

// =====================================================================
// launch
// =====================================================================
extern "C" void kernel_launch(void* const* d_in, const int* in_sizes, int n_in,
                              void* d_out, int out_size)
{
    (void)in_sizes; (void)n_in; (void)out_size;
    const float* x        = (const float*)d_in[0];
    const float* conv_w   = (const float*)d_in[1];
    const float* conv_b   = (const float*)d_in[2];
    const float* norm_w   = (const float*)d_in[3];
    const float* inp_w    = (const float*)d_in[4];
    const float* inp_b    = (const float*)d_in[5];
    const float* seqconv_w= (const float*)d_in[6];
    const float* seqconv_b= (const float*)d_in[7];
    const float* convlin_w= (const float*)d_in[8];
    const float* convlin_b= (const float*)d_in[9];
    const float* fc1_w    = (const float*)d_in[10];
    const float* fc1_b    = (const float*)d_in[11];
    const float* fc2_w    = (const float*)d_in[12];
    const float* fc2_b    = (const float*)d_in[13];
    const float* fc3_w    = (const float*)d_in[14];
    const float* fc3_b    = (const float*)d_in[15];
    const float* A        = (const float*)d_in[16];
    const float* D_w      = (const float*)d_in[17];
    const float* D_b      = (const float*)d_in[18];
    const float* out_w    = (const float*)d_in[19];
    const float* out_b    = (const float*)d_in[20];
    const float* fnn1_w   = (const float*)d_in[21];
    const float* fnn1_b   = (const float*)d_in[22];
    const float* fnn2_w   = (const float*)d_in[23];
    const float* fnn2_b   = (const float*)d_in[24];
    float* out = (float*)d_out;

    float *xn, *xp, *xc1, *xc, *delta, *dg, *Bm, *Cm, *xs, *yout, *fp, *aval;
    int *flag;
    cudaGetSymbolAddress((void**)&xn,    g_xn);
    cudaGetSymbolAddress((void**)&xp,    g_xp);
    cudaGetSymbolAddress((void**)&xc1,   g_xc1);
    cudaGetSymbolAddress((void**)&xc,    g_xc);
    cudaGetSymbolAddress((void**)&delta, g_delta);
    cudaGetSymbolAddress((void**)&dg,    g_dg);
    cudaGetSymbolAddress((void**)&Bm,    g_Bm);
    cudaGetSymbolAddress((void**)&Cm,    g_Cm);
    cudaGetSymbolAddress((void**)&xs,    g_xs);
    cudaGetSymbolAddress((void**)&yout,  g_yout);
    cudaGetSymbolAddress((void**)&fp,    g_fp);
    cudaGetSymbolAddress((void**)&aval,  g_aval);
    cudaGetSymbolAddress((void**)&flag,  g_flag);

    constexpr int SM_BIG = gemm_smem_bytes<128,64>();  // 55296
    constexpr int SM_SML = gemm_smem_bytes<64,64>();   // 36864
    cudaFuncSetAttribute(gemm_tc<128,64,4,2>,
                         cudaFuncAttributeMaxDynamicSharedMemorySize, SM_BIG);
    cudaFuncSetAttribute(gemm_tc<64,64,2,4>,
                         cudaFuncAttributeMaxDynamicSharedMemorySize, SM_SML);

    // 1) conv + rmsnorm (+ A prep in extra block)
    k_conv_prep<<<BATCH+1, 256>>>(x, conv_w, conv_b, norm_w, A, xn, flag, aval);

    // 2) fused: xp | dg    N=512, K=128
    {
        Seg3 s{};
        s.W[0]=inp_w; s.bias[0]=inp_b; s.out[0]=xp; s.act[0]=ACT_NONE; s.ldout[0]=DI;
        s.W[1]=D_w;   s.bias[1]=D_b;   s.out[1]=dg; s.act[1]=ACT_SILU; s.ldout[1]=DI;
        s.start[0]=0; s.start[1]=256; s.start[2]=INT_MAX; s.start[3]=INT_MAX;
        gemm_tc<128,64,4,2><<<dim3(8, MROWS/128), 256, SM_BIG>>>(xn, s, DMODEL);
    }

    // 3) seq conv + silu (j-quad threads)
    k_seqconv<<<dim3(BATCH, 2), 128>>>(xp, seqconv_w, seqconv_b, xc1);

    // 4) xc = xc1 @ convlin^T + b   N=256, K=256
    {
        Seg3 s{};
        s.W[0]=convlin_w; s.bias[0]=convlin_b; s.out[0]=xc; s.act[0]=ACT_NONE; s.ldout[0]=DI;
        s.start[0]=0; s.start[1]=INT_MAX; s.start[2]=INT_MAX; s.start[3]=INT_MAX;
        gemm_tc<128,64,4,2><<<dim3(4, MROWS/128), 256, SM_BIG>>>(xc1, s, DI);
    }

    // 5) fused: delta | Bm | Cm    N=512, K=256
    {
        Seg3 s{};
        s.W[0]=fc1_w; s.bias[0]=fc1_b; s.out[0]=delta; s.act[0]=ACT_SOFTPLUS; s.ldout[0]=DI;
        s.W[1]=fc2_w; s.bias[1]=fc2_b; s.out[1]=Bm;    s.act[1]=ACT_NONE;     s.ldout[1]=NSTATE;
        s.W[2]=fc3_w; s.bias[2]=fc3_b; s.out[2]=Cm;    s.act[2]=ACT_NONE;     s.ldout[2]=NSTATE;
        s.start[0]=0; s.start[1]=256; s.start[2]=384; s.start[3]=512;
        gemm_tc<128,64,4,2><<<dim3(8, MROWS/128), 256, SM_BIG>>>(xc, s, DI);
    }

    // 6) scan (merged fast/fallback)
    k_scan<<<BATCH, 256>>>(delta, Bm, Cm, xc, A, dg, aval, flag, xs);

    // 7) yout = xs @ out_w^T + b   N=128, K=256
    {
        Seg3 s{};
        s.W[0]=out_w; s.bias[0]=out_b; s.out[0]=yout; s.act[0]=ACT_NONE; s.ldout[0]=DMODEL;
        s.start[0]=0; s.start[1]=INT_MAX; s.start[2]=INT_MAX; s.start[3]=INT_MAX;
        gemm_tc<64,64,2,4><<<dim3(2, MROWS/64), 256, SM_SML>>>(xs, s, DI);
    }

    // 8) FNN head: split-K partials + finish
    k_fnn1p<<<dim3(BATCH/4, KSLICES), 256>>>(yout, fnn1_w, fp);
    k_fnn2<<<BATCH, 64>>>(fp, fnn1_b, fnn2_w, fnn2_b, out);
}

// round 16
// speedup vs baseline: 1.0572x; 1.0572x over previous
#include <cuda_runtime.h>
#include <math.h>
#include <limits.h>
#include <stdint.h>

// ---------------- problem constants ----------------
#define BATCH   256
#define LSEQ    34
#define DMODEL  128
#define DI      256
#define NSTATE  128
#define BAND    189
#define MROWS   (BATCH*LSEQ)   // 8704
#define KFLAT   (LSEQ*DMODEL)  // 4352
#define KCH     544            // 4352 / 8 slices
#define KSLICES 8

// ---------------- scratch (device globals; no runtime alloc) ----------------
__device__ float g_xn   [MROWS*DMODEL];
__device__ float g_xp   [MROWS*DI];
__device__ float g_xc1  [MROWS*DI];
__device__ float g_xc   [MROWS*DI];
__device__ float g_delta[MROWS*DI];
__device__ float g_dg   [MROWS*DI];
__device__ float g_Bm   [MROWS*NSTATE];
__device__ float g_Cm   [MROWS*NSTATE];
__device__ float g_xs   [MROWS*DI];   // holds silu(xs)*dg after scan
__device__ float g_yout [MROWS*DMODEL];
__device__ float g_fp   [KSLICES*BATCH*64];   // fnn1 split-K partials
__device__ float g_aval [DI];         // per-row A value (if uniform)
__device__ int   g_flag [1];          // 1 = all A rows uniform

// ---------------- math helpers ----------------
__device__ __forceinline__ float siluf(float x)     { return x / (1.0f + __expf(-x)); }
__device__ __forceinline__ float softplusf(float x) { return x > 15.0f ? x : log1pf(__expf(x)); }
__device__ __forceinline__ float leakyf(float x)    { return x >= 0.0f ? x : 0.01f * x; }

// ---------------- PTX helpers ----------------
__device__ __forceinline__ void cp16(uint32_t dst, const void* src) {
    asm volatile("cp.async.ca.shared.global [%0], [%1], 16;" :: "r"(dst), "l"(src));
}
__device__ __forceinline__ void ldsm_x4(uint32_t& r0, uint32_t& r1, uint32_t& r2, uint32_t& r3,
                                        uint32_t addr) {
    asm volatile("ldmatrix.sync.aligned.m8n8.x4.shared.b16 {%0,%1,%2,%3}, [%4];"
                 : "=r"(r0), "=r"(r1), "=r"(r2), "=r"(r3) : "r"(addr));
}
__device__ __forceinline__ void mma_tf32(float* c, const uint32_t* a, const uint32_t* b) {
    asm volatile("mma.sync.aligned.m16n8k8.row.col.f32.tf32.tf32.f32 "
                 "{%0,%1,%2,%3},{%4,%5,%6,%7},{%8,%9},{%0,%1,%2,%3};"
                 : "+f"(c[0]), "+f"(c[1]), "+f"(c[2]), "+f"(c[3])
                 : "r"(a[0]), "r"(a[1]), "r"(a[2]), "r"(a[3]), "r"(b[0]), "r"(b[1]));
}

// =====================================================================
// K1: conv1d + LeakyReLU + RMSNorm -> xn   (+ A-uniformity prep block)
// =====================================================================
__global__ __launch_bounds__(256)
void k_conv_prep(const float* __restrict__ x, const float* __restrict__ cw,
                 const float* __restrict__ cb, const float* __restrict__ nw,
                 const float* __restrict__ A,  float* __restrict__ xn,
                 int* __restrict__ flag, float* __restrict__ aval)
{
    int tid = threadIdx.x;

    if (blockIdx.x == BATCH) {
        int d = tid;
        const float* row = A + (size_t)d * NSTATE;
        float a0 = row[0];
        bool uni = true;
        #pragma unroll 8
        for (int n = 1; n < NSTATE; n++) uni &= (row[n] == a0);
        aval[d] = a0;
        int all = __syncthreads_and(uni ? 1 : 0);
        if (d == 0) flag[0] = all;
        return;
    }

    int b = blockIdx.x;
    int c = tid;
    bool active = (c < 128);

    __shared__ float sx[BAND];
    __shared__ float sw[128*21];
    __shared__ float red[2][4];

    for (int i = tid; i < 128*20; i += 256) sw[(i/20)*21 + (i%20)] = cw[i];
    for (int i = tid; i < BAND; i += 256)   sx[i] = x[b*BAND + i];
    __syncthreads();

    float wreg[20];
    float cbv = 0.f, nwv = 0.f;
    if (active) {
        #pragma unroll
        for (int k = 0; k < 20; k++) wreg[k] = sw[c*21 + k];
        cbv = cb[c]; nwv = nw[c];
    }

    #pragma unroll 1
    for (int l = 0; l < LSEQ; l++) {
        float acc = cbv;
        if (active) {
            #pragma unroll
            for (int k = 0; k < 20; k++) acc = fmaf(sx[l*5 + k], wreg[k], acc);
            acc = leakyf(acc);
        }
        float sq = acc * acc;
        #pragma unroll
        for (int off = 16; off; off >>= 1) sq += __shfl_xor_sync(0xffffffffu, sq, off);
        int pb = l & 1;
        if (active && (c & 31) == 0) red[pb][c >> 5] = sq;
        __syncthreads();
        if (active) {
            float inv = rsqrtf((red[pb][0]+red[pb][1]+red[pb][2]+red[pb][3])
                               * (1.0f/128.0f) + 1e-5f);
            xn[(b*LSEQ + l)*DMODEL + c] = acc * inv * nwv;
        }
    }
}

// =====================================================================
// Segmented TF32 tensor-core GEMM, 3-stage cp.async pipeline, BK=32,
// single __syncthreads per iteration.
// =====================================================================
#define ACT_NONE 0
#define ACT_SILU 1
#define ACT_SOFTPLUS 2

struct Seg3 {
    const float* W[3];
    const float* bias[3];
    float*       out[3];
    int start[4];
    int act[3];
    int ldout[3];
};

template<int BM, int BN, int WM, int WN>
__global__ __launch_bounds__(256)
void gemm_tc(const float* __restrict__ A, Seg3 segs, int K)
{
    constexpr int BK   = 32;
    constexpr int LD   = BK + 4;
    constexpr int STG  = 3;
    constexpr int CPR  = BK / 4;
    constexpr int WTM  = BM / WM;
    constexpr int WTN  = BN / WN;
    constexpr int AM   = WTM / 16;
    constexpr int AN   = WTN / 8;

    extern __shared__ __align__(16) float smem[];
    float* As = smem;
    float* Ws = smem + STG * BM * LD;

    const int tid  = threadIdx.x;
    const int lane = tid & 31;
    const int warp = tid >> 5;
    const int wm   = warp % WM;
    const int wn   = warp / WM;

    const int bm = blockIdx.y * BM;
    const int n0 = blockIdx.x * BN;

    int s = 0;
    if (n0 >= segs.start[1]) s = 1;
    if (n0 >= segs.start[2]) s = 2;
    const float* __restrict__ W = segs.W[s];
    const int ln0 = n0 - segs.start[s];

    const uint32_t sA0 = (uint32_t)__cvta_generic_to_shared(As);
    const uint32_t sW0 = (uint32_t)__cvta_generic_to_shared(Ws);

    float acc[AM][AN][4];
    #pragma unroll
    for (int i = 0; i < AM; i++)
        #pragma unroll
        for (int j = 0; j < AN; j++)
            #pragma unroll
            for (int q = 0; q < 4; q++) acc[i][j][q] = 0.0f;

    auto load_tiles = [&](int buf, int k0) {
        uint32_t dA = sA0 + (uint32_t)buf * (BM*LD*4);
        #pragma unroll
        for (int t = 0; t < (BM*CPR)/256; t++) {
            int c = tid + t*256;
            int row = c / CPR, kc = (c % CPR)*4;
            cp16(dA + (uint32_t)(row*LD + kc)*4, A + (size_t)(bm+row)*K + k0 + kc);
        }
        uint32_t dW = sW0 + (uint32_t)buf * (BN*LD*4);
        #pragma unroll
        for (int t = 0; t < (BN*CPR)/256; t++) {
            int c = tid + t*256;
            int row = c / CPR, kc = (c % CPR)*4;
            cp16(dW + (uint32_t)(row*LD + kc)*4, W + (size_t)(ln0+row)*K + k0 + kc);
        }
        asm volatile("cp.async.commit_group;");
    };

    const int a_row_in = ((lane >> 3) & 1) * 8 + (lane & 7);
    const int a_bc_hi  = (lane >= 16) ? 16 : 0;
    const int b_row_in = ((lane >= 16) ? 8 : 0) + (lane & 7);
    const int b_bc_hi  = ((lane >> 3) & 1) * 16;

    auto compute = [&](int buf) {
        const uint32_t aB = sA0 + (uint32_t)buf * (BM*LD*4);
        const uint32_t wB = sW0 + (uint32_t)buf * (BN*LD*4);
        #pragma unroll
        for (int k8 = 0; k8 < BK; k8 += 8) {
            uint32_t af[AM][4];
            #pragma unroll
            for (int mi = 0; mi < AM; mi++) {
                int r = wm*WTM + mi*16 + a_row_in;
                ldsm_x4(af[mi][0], af[mi][1], af[mi][2], af[mi][3],
                        aB + (uint32_t)(r*LD)*4 + (uint32_t)(k8*4 + a_bc_hi));
            }
            uint32_t bf[AN][2];
            #pragma unroll
            for (int nj = 0; nj < AN; nj += 2) {
                int r = wn*WTN + nj*8 + b_row_in;
                ldsm_x4(bf[nj][0], bf[nj][1], bf[nj+1][0], bf[nj+1][1],
                        wB + (uint32_t)(r*LD)*4 + (uint32_t)(k8*4 + b_bc_hi));
            }
            #pragma unroll
            for (int mi = 0; mi < AM; mi++)
                #pragma unroll
                for (int nj = 0; nj < AN; nj++)
                    mma_tf32(acc[mi][nj], af[mi], bf[nj]);
        }
    };

    const int NIT = K / BK;
    load_tiles(0, 0);
    load_tiles(1, BK);
    for (int it = 0; it < NIT; it++) {
        if (it + 2 < NIT) asm volatile("cp.async.wait_group 1;");
        else              asm volatile("cp.async.wait_group 0;");
        __syncthreads();
        if (it + 2 < NIT) load_tiles((it+2) % STG, (it+2) * BK);
        compute(it % STG);
    }

    __syncthreads();
    const float* __restrict__ bias = segs.bias[s];
    float* __restrict__ outp = segs.out[s];
    const int ld  = segs.ldout[s];
    const int act = segs.act[s];

    #pragma unroll
    for (int mi = 0; mi < AM; mi++) {
        int row0 = bm + wm*WTM + mi*16 + (lane >> 2);
        #pragma unroll
        for (int nj = 0; nj < AN; nj++) {
            int col = ln0 + wn*WTN + nj*8 + ((lane & 3) << 1);
            float b0 = bias[col], b1 = bias[col+1];
            float v0 = acc[mi][nj][0] + b0;
            float v1 = acc[mi][nj][1] + b1;
            float v2 = acc[mi][nj][2] + b0;
            float v3 = acc[mi][nj][3] + b1;
            if (act == ACT_SILU) {
                v0 = siluf(v0); v1 = siluf(v1); v2 = siluf(v2); v3 = siluf(v3);
            } else if (act == ACT_SOFTPLUS) {
                v0 = softplusf(v0); v1 = softplusf(v1);
                v2 = softplusf(v2); v3 = softplusf(v3);
            }
            *(float2*)(outp + (size_t)row0*ld + col)     = make_float2(v0, v1);
            *(float2*)(outp + (size_t)(row0+8)*ld + col) = make_float2(v2, v3);
        }
    }
}

template<int BM, int BN>
constexpr int gemm_smem_bytes() { return 3 * (BM + BN) * 36 * 4; }

// =====================================================================
// K3: seq-conv + silu. 128 threads: thread = (j-quad, lo-quarter).
// grid (BATCH, 2).
// =====================================================================
__global__ __launch_bounds__(128)
void k_seqconv(const float* __restrict__ xp, const float* __restrict__ w,
               const float* __restrict__ bias, float* __restrict__ out)
{
    int b  = blockIdx.x;
    int jb = blockIdx.y * 128;
    int tid = threadIdx.x;
    int jq  = tid & 31;
    int q   = tid >> 5;
    const int j   = jq * 4;
    const int lo0 = (q < 2) ? q*9 : 18 + (q-2)*8;
    const int nlo = (q < 2) ? 9 : 8;

    __shared__ __align__(16) float4 sw4[LSEQ*LSEQ];   // [li][lo]
    __shared__ __align__(8)  float sx[LSEQ][130];
    __shared__ float sb[LSEQ];

    for (int i = tid; i < LSEQ*LSEQ; i += 128) {
        int li = i / LSEQ, lo = i % LSEQ;
        const float* wp = w + (lo*LSEQ + li)*3;
        sw4[i] = make_float4(wp[0], wp[1], wp[2], 0.0f);
    }
    if (tid < LSEQ) sb[tid] = bias[tid];
    for (int i = tid; i < LSEQ*128; i += 128) {
        int l = i >> 7, jj = i & 127;
        sx[l][jj+1] = xp[(size_t)(b*LSEQ + l)*DI + jb + jj];
    }
    if (tid < LSEQ) {
        sx[tid][0]   = (jb == 0)   ? 0.0f : xp[(size_t)(b*LSEQ + tid)*DI + jb - 1];
        sx[tid][129] = (jb == 128) ? 0.0f : xp[(size_t)(b*LSEQ + tid)*DI + jb + 128];
    }
    __syncthreads();

    float acc[9][4];
    #pragma unroll
    for (int r = 0; r < 9; r++) {
        float bv = (r < nlo) ? sb[lo0 + r] : 0.0f;
        acc[r][0] = bv; acc[r][1] = bv; acc[r][2] = bv; acc[r][3] = bv;
    }

    #pragma unroll 2
    for (int li = 0; li < LSEQ; li++) {
        float2 x01 = *(const float2*)&sx[li][j];
        float2 x23 = *(const float2*)&sx[li][j+2];
        float2 x45 = *(const float2*)&sx[li][j+4];
        float x0 = x01.x, x1 = x01.y, x2 = x23.x, x3 = x23.y, x4 = x45.x, x5 = x45.y;
        const float4* wr = &sw4[li*LSEQ + lo0];
        #pragma unroll
        for (int r = 0; r < 9; r++) {
            if (r < nlo) {
                float4 wv = wr[r];
                acc[r][0] = fmaf(wv.x, x0, fmaf(wv.y, x1, fmaf(wv.z, x2, acc[r][0])));
                acc[r][1] = fmaf(wv.x, x1, fmaf(wv.y, x2, fmaf(wv.z, x3, acc[r][1])));
                acc[r][2] = fmaf(wv.x, x2, fmaf(wv.y, x3, fmaf(wv.z, x4, acc[r][2])));
                acc[r][3] = fmaf(wv.x, x3, fmaf(wv.y, x4, fmaf(wv.z, x5, acc[r][3])));
            }
        }
    }
    #pragma unroll
    for (int r = 0; r < 9; r++) {
        if (r < nlo) {
            float4 v = make_float4(siluf(acc[r][0]), siluf(acc[r][1]),
                                   siluf(acc[r][2]), siluf(acc[r][3]));
            *(float4*)(out + (size_t)(b*LSEQ + lo0 + r)*DI + jb + j) = v;
        }
    }
}

// =====================================================================
// K7: scan (merged fast/fallback). grid BATCH x 256.
// =====================================================================
__global__ __launch_bounds__(256)
void k_scan(const float* __restrict__ delta, const float* __restrict__ Bm,
            const float* __restrict__ Cm,    const float* __restrict__ xc,
            const float* __restrict__ A,     const float* __restrict__ dgp,
            const float* __restrict__ aval,  const int* __restrict__ flag,
            float* __restrict__ xs)
{
    int b = blockIdx.x;
    int tid = threadIdx.x;
    int lane = tid & 31, warp = tid >> 5;

    if (flag[0]) {
        __shared__ float sC [LSEQ*132];
        __shared__ float sBt[NSTATE*36];
        __shared__ float sG [LSEQ*36];

        for (int i = tid; i < LSEQ*NSTATE; i += 256) {
            int l = i >> 7, n = i & 127;
            sC[l*132 + n] = Cm[(size_t)b*LSEQ*NSTATE + i];
            sBt[n*36 + l] = Bm[(size_t)b*LSEQ*NSTATE + i];
        }
        __syncthreads();

        {
            int l0 = warp * 4;
            float a0[4], a1[4];
            #pragma unroll
            for (int r = 0; r < 4; r++) { a0[r] = 0.f; a1[r] = 0.f; }
            #pragma unroll 4
            for (int n = 0; n < NSTATE; n++) {
                float bv0 = sBt[n*36 + lane];
                float bv1 = (lane < 2) ? sBt[n*36 + 32 + lane] : 0.0f;
                #pragma unroll
                for (int r = 0; r < 4; r++) {
                    float cv = sC[(l0+r)*132 + n];
                    a0[r] = fmaf(cv, bv0, a0[r]);
                    a1[r] = fmaf(cv, bv1, a1[r]);
                }
            }
            #pragma unroll
            for (int r = 0; r < 4; r++) {
                sG[(l0+r)*36 + lane] = a0[r];
                if (lane < 2) sG[(l0+r)*36 + 32 + lane] = a1[r];
            }
            if (warp < 2) {
                int l = 32 + warp;
                float e0 = 0.f, e1 = 0.f;
                #pragma unroll 4
                for (int n = 0; n < NSTATE; n++) {
                    float bv0 = sBt[n*36 + lane];
                    float bv1 = (lane < 2) ? sBt[n*36 + 32 + lane] : 0.0f;
                    float cv  = sC[l*132 + n];
                    e0 = fmaf(cv, bv0, e0);
                    e1 = fmaf(cv, bv1, e1);
                }
                sG[l*36 + lane] = e0;
                if (lane < 2) sG[l*36 + 32 + lane] = e1;
            }
        }

        int d = tid;
        const float av = aval[d];

        float S[LSEQ], dx[LSEQ];
        #pragma unroll
        for (int l = 0; l < LSEQ; l++) {
            float dl = delta[((size_t)b*LSEQ + l)*DI + d];
            float xv = xc   [((size_t)b*LSEQ + l)*DI + d];
            S[l]  = dl * av;
            dx[l] = dl * xv;
        }
        #pragma unroll
        for (int l = 1; l < LSEQ; l++) S[l] += S[l-1];
        float m = fmaxf(S[0], S[LSEQ-1]);
        #pragma unroll
        for (int t = 0; t < LSEQ; t++) dx[t] *= __expf(m - S[t]);

        __syncthreads();

        #pragma unroll
        for (int l = 0; l < LSEQ; l++) {
            float y = 0.0f;
            const float* gr = &sG[l*36];
            #pragma unroll
            for (int t = 0; t <= l; t++)
                y = fmaf(gr[t], dx[t], y);
            float o = __expf(S[l] - m) * y;
            size_t idx = ((size_t)b*LSEQ + l)*DI + d;
            xs[idx] = siluf(o) * dgp[idx];
        }
    } else {
        // general-A fallback: warp per channel, strided. Correct, slow.
        for (int dd = warp; dd < DI; dd += 8) {
            float a0 = A[dd*NSTATE + lane +  0];
            float a1 = A[dd*NSTATE + lane + 32];
            float a2 = A[dd*NSTATE + lane + 64];
            float a3 = A[dd*NSTATE + lane + 96];
            float h0 = 0.f, h1 = 0.f, h2 = 0.f, h3 = 0.f;
            #pragma unroll 1
            for (int l = 0; l < LSEQ; l++) {
                size_t ridx = (size_t)b*LSEQ + l;
                float dv = delta[ridx*DI + dd];
                float xv = xc   [ridx*DI + dd];
                float dx = dv * xv;
                const float* Brow = Bm + ridx*NSTATE;
                const float* Crow = Cm + ridx*NSTATE;
                h0 = fmaf(__expf(dv*a0), h0, dx * Brow[lane +  0]);
                h1 = fmaf(__expf(dv*a1), h1, dx * Brow[lane + 32]);
                h2 = fmaf(__expf(dv*a2), h2, dx * Brow[lane + 64]);
                h3 = fmaf(__expf(dv*a3), h3, dx * Brow[lane + 96]);
                float acc = Crow[lane+0]*h0 + Crow[lane+32]*h1
                          + Crow[lane+64]*h2 + Crow[lane+96]*h3;
                #pragma unroll
                for (int off = 16; off; off >>= 1)
                    acc += __shfl_down_sync(0xffffffffu, acc, off);
                if (lane == 0) {
                    size_t idx = ridx*DI + dd;
                    xs[idx] = siluf(acc) * dgp[idx];
                }
            }
        }
    }
}

// =====================================================================
// K9a: FNN1 split-K partials. grid (64, 8): 4 batches x 544-K-slice.
// =====================================================================
__global__ __launch_bounds__(256)
void k_fnn1p(const float* __restrict__ yflat, const float* __restrict__ w1,
             float* __restrict__ fp)
{
    int bg = blockIdx.x;
    int ks = blockIdx.y;
    int tid = threadIdx.x;
    int b0 = bg*4, k0 = ks*KCH;

    __shared__ float sy[4][KCH];
    for (int i = tid; i < 4*KCH; i += 256) {
        int bb = i / KCH, kk = i % KCH;
        sy[bb][kk] = yflat[(size_t)(b0+bb)*KFLAT + k0 + kk];
    }
    __syncthreads();

    int o = tid & 63, bb = tid >> 6;
    const float* wr = w1 + (size_t)o*KFLAT + k0;
    const float* yr = sy[bb];
    float acc = 0.0f;
    #pragma unroll 4
    for (int i = 0; i < KCH; i += 4) {
        float4 wv = *(const float4*)(wr + i);
        acc = fmaf(wv.x, yr[i+0], acc);
        acc = fmaf(wv.y, yr[i+1], acc);
        acc = fmaf(wv.z, yr[i+2], acc);
        acc = fmaf(wv.w, yr[i+3], acc);
    }
    fp[((size_t)ks*BATCH + b0 + bb)*64 + o] = acc;
}

// =====================================================================
// K9b: FNN finish: reduce partials + bias + leaky, then FNN2.
// =====================================================================
__global__ __launch_bounds__(64)
void k_fnn2(const float* __restrict__ fp, const float* __restrict__ b1,
            const float* __restrict__ w2, const float* __restrict__ b2,
            float* __restrict__ out)
{
    int b = blockIdx.x;
    int o = threadIdx.x;
    __shared__ float sf[64];

    float acc = b1[o];
    #pragma unroll
    for (int ks = 0; ks < KSLICES; ks++)
        acc += fp[((size_t)ks*BATCH + b)*64 + o];
    sf[o] = leakyf(acc);
    __syncthreads();

    if (o < 32) {
        float a2 = b2[o];
        #pragma unroll 8
        for (int j = 0; j < 64; j++) a2 = fmaf(sf[j], w2[o*64 + j], a2);
        out[(size_t)b*32 + o] = a2;
    }
}

// =====================================================================
// launch
// =====================================================================
extern "C" void kernel_launch(void* const* d_in, const int* in_sizes, int n_in,
                              void* d_out, int out_size)
{
    (void)in_sizes; (void)n_in; (void)out_size;
    const float* x        = (const float*)d_in[0];
    const float* conv_w   = (const float*)d_in[1];
    const float* conv_b   = (const float*)d_in[2];
    const float* norm_w   = (const float*)d_in[3];
    const float* inp_w    = (const float*)d_in[4];
    const float* inp_b    = (const float*)d_in[5];
    const float* seqconv_w= (const float*)d_in[6];
    const float* seqconv_b= (const float*)d_in[7];
    const float* convlin_w= (const float*)d_in[8];
    const float* convlin_b= (const float*)d_in[9];
    const float* fc1_w    = (const float*)d_in[10];
    const float* fc1_b    = (const float*)d_in[11];
    const float* fc2_w    = (const float*)d_in[12];
    const float* fc2_b    = (const float*)d_in[13];
    const float* fc3_w    = (const float*)d_in[14];
    const float* fc3_b    = (const float*)d_in[15];
    const float* A        = (const float*)d_in[16];
    const float* D_w      = (const float*)d_in[17];
    const float* D_b      = (const float*)d_in[18];
    const float* out_w    = (const float*)d_in[19];
    const float* out_b    = (const float*)d_in[20];
    const float* fnn1_w   = (const float*)d_in[21];
    const float* fnn1_b   = (const float*)d_in[22];
    const float* fnn2_w   = (const float*)d_in[23];
    const float* fnn2_b   = (const float*)d_in[24];
    float* out = (float*)d_out;

    float *xn, *xp, *xc1, *xc, *delta, *dg, *Bm, *Cm, *xs, *yout, *fp, *aval;
    int *flag;
    cudaGetSymbolAddress((void**)&xn,    g_xn);
    cudaGetSymbolAddress((void**)&xp,    g_xp);
    cudaGetSymbolAddress((void**)&xc1,   g_xc1);
    cudaGetSymbolAddress((void**)&xc,    g_xc);
    cudaGetSymbolAddress((void**)&delta, g_delta);
    cudaGetSymbolAddress((void**)&dg,    g_dg);
    cudaGetSymbolAddress((void**)&Bm,    g_Bm);
    cudaGetSymbolAddress((void**)&Cm,    g_Cm);
    cudaGetSymbolAddress((void**)&xs,    g_xs);
    cudaGetSymbolAddress((void**)&yout,  g_yout);
    cudaGetSymbolAddress((void**)&fp,    g_fp);
    cudaGetSymbolAddress((void**)&aval,  g_aval);
    cudaGetSymbolAddress((void**)&flag,  g_flag);

    constexpr int SM_WIDE = gemm_smem_bytes<128,128>(); // 110592
    constexpr int SM_BIG  = gemm_smem_bytes<128,64>();  // 82944
    constexpr int SM_SML  = gemm_smem_bytes<64,64>();   // 55296
    cudaFuncSetAttribute(gemm_tc<128,128,4,2>,
                         cudaFuncAttributeMaxDynamicSharedMemorySize, SM_WIDE);
    cudaFuncSetAttribute(gemm_tc<128,64,4,2>,
                         cudaFuncAttributeMaxDynamicSharedMemorySize, SM_BIG);
    cudaFuncSetAttribute(gemm_tc<64,64,2,4>,
                         cudaFuncAttributeMaxDynamicSharedMemorySize, SM_SML);

    // 1) conv + rmsnorm (+ A prep in extra block)
    k_conv_prep<<<BATCH+1, 256>>>(x, conv_w, conv_b, norm_w, A, xn, flag, aval);

    // 2) fused: xp | dg    N=512, K=128  (BN=128 -> 272 CTAs, AN=8)
    {
        Seg3 s{};
        s.W[0]=inp_w; s.bias[0]=inp_b; s.out[0]=xp; s.act[0]=ACT_NONE; s.ldout[0]=DI;
        s.W[1]=D_w;   s.bias[1]=D_b;   s.out[1]=dg; s.act[1]=ACT_SILU; s.ldout[1]=DI;
        s.start[0]=0; s.start[1]=256; s.start[2]=INT_MAX; s.start[3]=INT_MAX;
        gemm_tc<128,128,4,2><<<dim3(4, MROWS/128), 256, SM_WIDE>>>(xn, s, DMODEL);
    }

    // 3) seq conv + silu (j-quad threads)
    k_seqconv<<<dim3(BATCH, 2), 128>>>(xp, seqconv_w, seqconv_b, xc1);

    // 4) xc = xc1 @ convlin^T + b   N=256, K=256  (BN=64 -> 272 CTAs)
    {
        Seg3 s{};
        s.W[0]=convlin_w; s.bias[0]=convlin_b; s.out[0]=xc; s.act[0]=ACT_NONE; s.ldout[0]=DI;
        s.start[0]=0; s.start[1]=INT_MAX; s.start[2]=INT_MAX; s.start[3]=INT_MAX;
        gemm_tc<128,64,4,2><<<dim3(4, MROWS/128), 256, SM_BIG>>>(xc1, s, DI);
    }

    // 5) fused: delta | Bm | Cm    N=512, K=256  (BN=128 -> 272 CTAs, AN=8)
    {
        Seg3 s{};
        s.W[0]=fc1_w; s.bias[0]=fc1_b; s.out[0]=delta; s.act[0]=ACT_SOFTPLUS; s.ldout[0]=DI;
        s.W[1]=fc2_w; s.bias[1]=fc2_b; s.out[1]=Bm;    s.act[1]=ACT_NONE;     s.ldout[1]=NSTATE;
        s.W[2]=fc3_w; s.bias[2]=fc3_b; s.out[2]=Cm;    s.act[2]=ACT_NONE;     s.ldout[2]=NSTATE;
        s.start[0]=0; s.start[1]=256; s.start[2]=384; s.start[3]=512;
        gemm_tc<128,128,4,2><<<dim3(4, MROWS/128), 256, SM_WIDE>>>(xc, s, DI);
    }

    // 6) scan (merged fast/fallback)
    k_scan<<<BATCH, 256>>>(delta, Bm, Cm, xc, A, dg, aval, flag, xs);

    // 7) yout = xs @ out_w^T + b   N=128, K=256
    {
        Seg3 s{};
        s.W[0]=out_w; s.bias[0]=out_b; s.out[0]=yout; s.act[0]=ACT_NONE; s.ldout[0]=DMODEL;
        s.start[0]=0; s.start[1]=INT_MAX; s.start[2]=INT_MAX; s.start[3]=INT_MAX;
        gemm_tc<64,64,2,4><<<dim3(2, MROWS/64), 256, SM_SML>>>(xs, s, DI);
    }

    // 8) FNN head: split-K partials + finish
    k_fnn1p<<<dim3(BATCH/4, KSLICES), 256>>>(yout, fnn1_w, fp);
    k_fnn2<<<BATCH, 64>>>(fp, fnn1_b, fnn2_w, fnn2_b, out);
}